// round 2
// baseline (speedup 1.0000x reference)
#include <cuda_runtime.h>
#include <cstdint>
#include <cstddef>

#define NN 20000
#define EE 640000
#define HH 128
#define LL 10

typedef unsigned long long u64;

__device__ float g_h[(size_t)NN * HH];
__device__ float g_hagg[(size_t)NN * HH];
__device__ float g_e[(size_t)EE * HH];
__device__ int   g_src[EE];
__device__ int   g_dst[EE];
__device__ int   g_is64;

__device__ __forceinline__ u64 bcast2(float x) {
    u64 r; unsigned u = __float_as_uint(x);
    asm("mov.b64 %0, {%1, %1};" : "=l"(r) : "r"(u));
    return r;
}
__device__ __forceinline__ u64 fma2(u64 a, u64 b, u64 c) {
    u64 d;
    asm("fma.rn.f32x2 %0, %1, %2, %3;" : "=l"(d) : "l"(a), "l"(b), "l"(c));
    return d;
}
__device__ __forceinline__ void unpack2(u64 v, float& x, float& y) {
    unsigned lo, hi;
    asm("mov.b64 {%0, %1}, %2;" : "=r"(lo), "=r"(hi) : "l"(v));
    x = __uint_as_float(lo); y = __uint_as_float(hi);
}
__device__ __forceinline__ void red4(float* p, float a, float b, float c, float d) {
    asm volatile("red.global.add.v4.f32 [%0], {%1,%2,%3,%4};"
                 :: "l"(p), "f"(a), "f"(b), "f"(c), "f"(d) : "memory");
}

// Tile GEMM: 64 rows x 128 cols, 256 threads. tx=tid&15 (8 cols), ty=tid>>4
// (4 rows). A in smem (stride AS), W streamed global->smem double-buffered
// in 32x128 chunks.
template<int K>
__device__ __forceinline__ void gemm_tile(const float* __restrict__ As, int AS,
                                          const float* __restrict__ Wg,
                                          float* __restrict__ Wb,
                                          u64 acc[16], int tid, int tx, int ty) {
    constexpr int CH  = (K < 32) ? K : 32;
    constexpr int NCH = K / CH;
    constexpr int LPT = (CH * HH) / (4 * 256);
    const float* ar0 = As + (ty * 4 + 0) * AS;
    const float* ar1 = ar0 + AS;
    const float* ar2 = ar1 + AS;
    const float* ar3 = ar2 + AS;
    float4 pre[LPT];
#pragma unroll
    for (int t = 0; t < LPT; t++) pre[t] = __ldg((const float4*)Wg + tid + t * 256);
#pragma unroll
    for (int t = 0; t < LPT; t++) ((float4*)Wb)[tid + t * 256] = pre[t];
#pragma unroll 1
    for (int c = 0; c < NCH; c++) {
        __syncthreads();
        if (c + 1 < NCH) {
#pragma unroll
            for (int t = 0; t < LPT; t++)
                pre[t] = __ldg((const float4*)(Wg + (size_t)(c + 1) * CH * HH) + tid + t * 256);
        }
        const float* wbase = Wb + (c & 1) * CH * HH + tx * 8;
        const int kb = c * CH;
#pragma unroll
        for (int kk = 0; kk < CH; kk++) {
            u64 p0 = bcast2(ar0[kb + kk]);
            u64 p1 = bcast2(ar1[kb + kk]);
            u64 p2 = bcast2(ar2[kb + kk]);
            u64 p3 = bcast2(ar3[kb + kk]);
            const float* wr = wbase + kk * HH;
            ulonglong2 wA = *(const ulonglong2*)(wr);
            ulonglong2 wB = *(const ulonglong2*)(wr + 4);
            acc[0]  = fma2(p0, wA.x, acc[0]);  acc[1]  = fma2(p0, wA.y, acc[1]);
            acc[2]  = fma2(p0, wB.x, acc[2]);  acc[3]  = fma2(p0, wB.y, acc[3]);
            acc[4]  = fma2(p1, wA.x, acc[4]);  acc[5]  = fma2(p1, wA.y, acc[5]);
            acc[6]  = fma2(p1, wB.x, acc[6]);  acc[7]  = fma2(p1, wB.y, acc[7]);
            acc[8]  = fma2(p2, wA.x, acc[8]);  acc[9]  = fma2(p2, wA.y, acc[9]);
            acc[10] = fma2(p2, wB.x, acc[10]); acc[11] = fma2(p2, wB.y, acc[11]);
            acc[12] = fma2(p3, wA.x, acc[12]); acc[13] = fma2(p3, wA.y, acc[13]);
            acc[14] = fma2(p3, wB.x, acc[14]); acc[15] = fma2(p3, wB.y, acc[15]);
        }
        if (c + 1 < NCH) {
#pragma unroll
            for (int t = 0; t < LPT; t++)
                ((float4*)(Wb + ((c + 1) & 1) * CH * HH))[tid + t * 256] = pre[t];
        }
    }
}

__device__ __forceinline__ void zero_acc(u64 acc[16]) {
#pragma unroll
    for (int i = 0; i < 16; i++) acc[i] = 0ull;
}

__device__ __forceinline__ void acc_finish(const u64 acc[16], const float* __restrict__ bg,
                                           int tx, float o[4][8]) {
    float4 b0 = __ldg((const float4*)(bg + tx * 8));
    float4 b1 = __ldg((const float4*)(bg + tx * 8) + 1);
#pragma unroll
    for (int i = 0; i < 4; i++) {
#pragma unroll
        for (int j = 0; j < 4; j++) unpack2(acc[i * 4 + j], o[i][2 * j], o[i][2 * j + 1]);
        o[i][0] += b0.x; o[i][1] += b0.y; o[i][2] += b0.z; o[i][3] += b0.w;
        o[i][4] += b1.x; o[i][5] += b1.y; o[i][6] += b1.z; o[i][7] += b1.w;
    }
}

__global__ void zero_hagg_kernel() {
    int i = blockIdx.x * blockDim.x + threadIdx.x;
    ((float4*)g_hagg)[i] = make_float4(0.f, 0.f, 0.f, 0.f);
}

__global__ void detect_idx_kernel(const int* raw) {
    if (threadIdx.x == 0) {
        int flag = 1;
#pragma unroll
        for (int t = 1; t < 16; t += 2) if (raw[t] != 0) flag = 0;
        g_is64 = flag;
    }
}

__global__ void convert_idx_kernel(const void* eidx) {
    int i = blockIdx.x * blockDim.x + threadIdx.x;
    if (i >= EE) return;
    if (g_is64) {
        const long long* p = (const long long*)eidx;
        g_src[i] = (int)p[i];
        g_dst[i] = (int)p[(size_t)EE + i];
    } else {
        const int* p = (const int*)eidx;
        g_src[i] = p[i];
        g_dst[i] = p[EE + i];
    }
}

__global__ void __launch_bounds__(256, 1)
node_enc_kernel(const float* __restrict__ x, const float* __restrict__ nz,
                const float* __restrict__ W1, const float* __restrict__ b1,
                const float* __restrict__ W2, const float* __restrict__ b2) {
    extern __shared__ float sm[];
    float* A   = sm;               // 64 x 20
    float* hid = sm + 64 * 20;     // 64 x 132
    float* Wb  = hid + 64 * 132;   // 2 x 32 x 128
    const int tid = threadIdx.x, tx = tid & 15, ty = tid >> 4;
    const int nb = blockIdx.x * 64;
    {
        int r = tid >> 2, c4 = tid & 3;
        float4 v = make_float4(0.f, 0.f, 0.f, 0.f);
        if (nb + r < NN) {
            float4 a = __ldg((const float4*)(x  + (size_t)(nb + r) * 16) + c4);
            float4 n = __ldg((const float4*)(nz + (size_t)(nb + r) * 16) + c4);
            v = make_float4(a.x + n.x, a.y + n.y, a.z + n.z, a.w + n.w);
        }
        *(float4*)(A + r * 20 + (c4 << 2)) = v;
    }
    __syncthreads();
    u64 acc[16]; float o[4][8];
    zero_acc(acc);
    gemm_tile<16>(A, 20, W1, Wb, acc, tid, tx, ty);
    acc_finish(acc, b1, tx, o);
#pragma unroll
    for (int i = 0; i < 4; i++)
#pragma unroll
        for (int j = 0; j < 8; j++)
            hid[(ty * 4 + i) * 132 + tx * 8 + j] = fmaxf(o[i][j], 0.f);
    __syncthreads();
    zero_acc(acc);
    gemm_tile<128>(hid, 132, W2, Wb, acc, tid, tx, ty);
    acc_finish(acc, b2, tx, o);
#pragma unroll
    for (int i = 0; i < 4; i++) {
        int r = ty * 4 + i;
        if (nb + r < NN) {
            float* p = g_h + (size_t)(nb + r) * HH + tx * 8;
            *(float4*)p       = make_float4(o[i][0], o[i][1], o[i][2], o[i][3]);
            *(float4*)(p + 4) = make_float4(o[i][4], o[i][5], o[i][6], o[i][7]);
        }
    }
}

__global__ void __launch_bounds__(256, 1)
edge_enc_kernel(const float* __restrict__ ea, const float* __restrict__ ez,
                const float* __restrict__ W1, const float* __restrict__ b1,
                const float* __restrict__ W2, const float* __restrict__ b2) {
    extern __shared__ float sm[];
    float* A   = sm;              // 64 x 12
    float* hid = sm + 64 * 12;
    float* Wb  = hid + 64 * 132;
    const int tid = threadIdx.x, tx = tid & 15, ty = tid >> 4;
    const int eb = blockIdx.x * 64;
    if (tid < 128) {
        int r = tid >> 1, c4 = tid & 1;
        float4 a = __ldg((const float4*)(ea + (size_t)(eb + r) * 8) + c4);
        float4 n = __ldg((const float4*)(ez + (size_t)(eb + r) * 8) + c4);
        *(float4*)(A + r * 12 + (c4 << 2)) =
            make_float4(a.x + n.x, a.y + n.y, a.z + n.z, a.w + n.w);
    }
    __syncthreads();
    u64 acc[16]; float o[4][8];
    zero_acc(acc);
    gemm_tile<8>(A, 12, W1, Wb, acc, tid, tx, ty);
    acc_finish(acc, b1, tx, o);
#pragma unroll
    for (int i = 0; i < 4; i++)
#pragma unroll
        for (int j = 0; j < 8; j++)
            hid[(ty * 4 + i) * 132 + tx * 8 + j] = fmaxf(o[i][j], 0.f);
    __syncthreads();
    zero_acc(acc);
    gemm_tile<128>(hid, 132, W2, Wb, acc, tid, tx, ty);
    acc_finish(acc, b2, tx, o);
#pragma unroll
    for (int i = 0; i < 4; i++) {
        int r = ty * 4 + i;
        float* p = g_e + (size_t)(eb + r) * HH + tx * 8;
        *(float4*)p       = make_float4(o[i][0], o[i][1], o[i][2], o[i][3]);
        *(float4*)(p + 4) = make_float4(o[i][4], o[i][5], o[i][6], o[i][7]);
    }
}

// Fused MPNN layer (edge side). A layout per row (stride 388):
// [0:128) xi | [128:256) xj then e_new | [256:384) e
__global__ void __launch_bounds__(256, 1)
layer_kernel(const float* __restrict__ We1, const float* __restrict__ be1,
             const float* __restrict__ We2, const float* __restrict__ be2,
             const float* __restrict__ Wn1, const float* __restrict__ bn1,
             const float* __restrict__ Wn2, const float* __restrict__ bn2,
             const float* __restrict__ lng, const float* __restrict__ lnb) {
    extern __shared__ float sm[];
    float* A   = sm;                       // 64 x 388
    float* hid = sm + 64 * 388;            // 64 x 132
    float* Wb  = hid + 64 * 132;           // 2 x 32 x 128
    int*  sdst = (int*)(Wb + 2 * 32 * HH);
    int*  ssrc = sdst + 64;

    const int tid = threadIdx.x, tx = tid & 15, ty = tid >> 4;
    const int eb = blockIdx.x * 64;

    if (tid < 64) { ssrc[tid] = g_src[eb + tid]; sdst[tid] = g_dst[eb + tid]; }
    __syncthreads();

#pragma unroll 1
    for (int t = 0; t < 24; t++) {
        int idx = tid + t * 256;
        int r = idx / 96, c4 = idx % 96;
        const float* s;
        if (c4 < 32)      s = g_h + (size_t)sdst[r] * HH + (c4 << 2);
        else if (c4 < 64) s = g_h + (size_t)ssrc[r] * HH + ((c4 - 32) << 2);
        else              s = g_e + (size_t)(eb + r) * HH + ((c4 - 64) << 2);
        *(float4*)(A + r * 388 + (c4 << 2)) = *(const float4*)s;
    }
    __syncthreads();

    u64 acc[16]; float o[4][8];

    zero_acc(acc);
    gemm_tile<384>(A, 388, We1, Wb, acc, tid, tx, ty);
    acc_finish(acc, be1, tx, o);
#pragma unroll
    for (int i = 0; i < 4; i++)
#pragma unroll
        for (int j = 0; j < 8; j++)
            hid[(ty * 4 + i) * 132 + tx * 8 + j] = fmaxf(o[i][j], 0.f);
    __syncthreads();

    zero_acc(acc);
    gemm_tile<128>(hid, 132, We2, Wb, acc, tid, tx, ty);
    acc_finish(acc, be2, tx, o);
    __syncthreads();
#pragma unroll
    for (int i = 0; i < 4; i++) {
        int r = ty * 4 + i;
#pragma unroll
        for (int j = 0; j < 8; j++)
            A[r * 388 + 128 + tx * 8 + j] = A[r * 388 + 256 + tx * 8 + j] + o[i][j];
    }
    __syncthreads();

    zero_acc(acc);
    gemm_tile<256>(A, 388, Wn1, Wb, acc, tid, tx, ty);
    acc_finish(acc, bn1, tx, o);
#pragma unroll
    for (int i = 0; i < 4; i++)
#pragma unroll
        for (int j = 0; j < 8; j++)
            hid[(ty * 4 + i) * 132 + tx * 8 + j] = fmaxf(o[i][j], 0.f);
    __syncthreads();

    zero_acc(acc);
    gemm_tile<128>(hid, 132, Wn2, Wb, acc, tid, tx, ty);
    acc_finish(acc, bn2, tx, o);
#pragma unroll
    for (int i = 0; i < 4; i++) {
        int r = ty * 4 + i;
        const float* xi = A + r * 388 + tx * 8;
        float* p = g_hagg + (size_t)sdst[r] * HH + tx * 8;
        red4(p,     xi[0] + o[i][0], xi[1] + o[i][1], xi[2] + o[i][2], xi[3] + o[i][3]);
        red4(p + 4, xi[4] + o[i][4], xi[5] + o[i][5], xi[6] + o[i][6], xi[7] + o[i][7]);
    }

    // edge LN: e_out = LN(e + e_new)
    {
        int r = tid >> 2, q = tid & 3;
        const float* pe  = A + r * 388 + 256 + q * 32;
        const float* pen = A + r * 388 + 128 + q * 32;
        float v[32];
#pragma unroll
        for (int c = 0; c < 32; c++) v[c] = pe[c] + pen[c];
        float s = 0.f;
#pragma unroll
        for (int c = 0; c < 32; c++) s += v[c];
        s += __shfl_xor_sync(0xffffffffu, s, 1);
        s += __shfl_xor_sync(0xffffffffu, s, 2);
        float m = s * (1.f / HH);
        float s2 = 0.f;
#pragma unroll
        for (int c = 0; c < 32; c++) { float d = v[c] - m; s2 += d * d; }
        s2 += __shfl_xor_sync(0xffffffffu, s2, 1);
        s2 += __shfl_xor_sync(0xffffffffu, s2, 2);
        float inv = rsqrtf(s2 * (1.f / HH) + 1e-5f);
        float* po = g_e + (size_t)(eb + r) * HH + q * 32;
        const float* gg = lng + q * 32;
        const float* bb = lnb + q * 32;
#pragma unroll
        for (int c = 0; c < 32; c++)
            po[c] = (v[c] - m) * inv * __ldg(gg + c) + __ldg(bb + c);
    }
}

__global__ void node_ln_kernel(const float* __restrict__ lg, const float* __restrict__ lb) {
    int tid = threadIdx.x;
    int r = blockIdx.x * 64 + (tid >> 2);
    int q = tid & 3;
    if (r >= NN) return;
    float v[32];
    const float4* ph = (const float4*)(g_h + (size_t)r * HH + q * 32);
    const float4* pa = (const float4*)(g_hagg + (size_t)r * HH + q * 32);
#pragma unroll
    for (int c = 0; c < 8; c++) {
        float4 a = ph[c], b = pa[c];
        v[4 * c + 0] = a.x + b.x; v[4 * c + 1] = a.y + b.y;
        v[4 * c + 2] = a.z + b.z; v[4 * c + 3] = a.w + b.w;
    }
    float s = 0.f;
#pragma unroll
    for (int c = 0; c < 32; c++) s += v[c];
    s += __shfl_xor_sync(0xffffffffu, s, 1);
    s += __shfl_xor_sync(0xffffffffu, s, 2);
    float m = s * (1.f / HH);
    float s2 = 0.f;
#pragma unroll
    for (int c = 0; c < 32; c++) { float d = v[c] - m; s2 += d * d; }
    s2 += __shfl_xor_sync(0xffffffffu, s2, 1);
    s2 += __shfl_xor_sync(0xffffffffu, s2, 2);
    float inv = rsqrtf(s2 * (1.f / HH) + 1e-5f);
    float* po = g_h + (size_t)r * HH + q * 32;
    const float* gg = lg + q * 32;
    const float* bb = lb + q * 32;
#pragma unroll
    for (int c = 0; c < 32; c++)
        po[c] = (v[c] - m) * inv * __ldg(gg + c) + __ldg(bb + c);
    float4 z = make_float4(0.f, 0.f, 0.f, 0.f);
    float4* pz = (float4*)(g_hagg + (size_t)r * HH + q * 32);
#pragma unroll
    for (int c = 0; c < 8; c++) pz[c] = z;
}

__global__ void __launch_bounds__(256, 1)
decoder_kernel(const float* __restrict__ W1, const float* __restrict__ b1,
               const float* __restrict__ W2, const float* __restrict__ b2,
               const float* __restrict__ nz, float* __restrict__ out) {
    extern __shared__ float sm[];
    float* A   = sm;               // 64 x 132
    float* hid = sm + 64 * 132;    // 64 x 132
    float* Wb  = hid + 64 * 132;   // 2 x 32 x 128
    float* W2s = Wb + 2 * 32 * HH; // 256
    const int tid = threadIdx.x, tx = tid & 15, ty = tid >> 4;
    const int nb = blockIdx.x * 64;
#pragma unroll 1
    for (int t = 0; t < 8; t++) {
        int idx = tid + t * 256;
        int r = idx >> 5, c4 = idx & 31;
        float4 v = make_float4(0.f, 0.f, 0.f, 0.f);
        if (nb + r < NN) v = __ldg((const float4*)(g_h + (size_t)(nb + r) * HH) + c4);
        *(float4*)(A + r * 132 + (c4 << 2)) = v;
    }
    if (tid < 256) W2s[tid] = __ldg(W2 + tid);
    __syncthreads();
    u64 acc[16]; float o[4][8];
    zero_acc(acc);
    gemm_tile<128>(A, 132, W1, Wb, acc, tid, tx, ty);
    acc_finish(acc, b1, tx, o);
#pragma unroll
    for (int i = 0; i < 4; i++)
#pragma unroll
        for (int j = 0; j < 8; j++)
            hid[(ty * 4 + i) * 132 + tx * 8 + j] = fmaxf(o[i][j], 0.f);
    __syncthreads();
    if (tid < 128) {
        int r = tid >> 1, c = tid & 1;
        if (nb + r < NN) {
            float s = 0.f;
            const float* hr = hid + r * 132;
#pragma unroll 8
            for (int k = 0; k < 128; k++) s += hr[k] * W2s[k * 2 + c];
            out[(size_t)(nb + r) * 2 + c] = s + __ldg(b2 + c)
                - __ldg(nz + (size_t)(nb + r) * 16 + c);
        }
    }
}

extern "C" void kernel_launch(void* const* d_in, const int* in_sizes, int n_in,
                              void* d_out, int out_size) {
    const float* x    = (const float*)d_in[0];
    const float* ea   = (const float*)d_in[1];
    const void*  eidx = d_in[2];
    const float* nz   = (const float*)d_in[3];
    const float* ez   = (const float*)d_in[4];
    const float* ne_w1 = (const float*)d_in[5],  *ne_b1 = (const float*)d_in[6];
    const float* ne_w2 = (const float*)d_in[7],  *ne_b2 = (const float*)d_in[8];
    const float* ee_w1 = (const float*)d_in[9],  *ee_b1 = (const float*)d_in[10];
    const float* ee_w2 = (const float*)d_in[11], *ee_b2 = (const float*)d_in[12];
    const float* ge_w1 = (const float*)d_in[13], *ge_b1 = (const float*)d_in[14];
    const float* ge_w2 = (const float*)d_in[15], *ge_b2 = (const float*)d_in[16];
    const float* gn_w1 = (const float*)d_in[17], *gn_b1 = (const float*)d_in[18];
    const float* gn_w2 = (const float*)d_in[19], *gn_b2 = (const float*)d_in[20];
    const float* xlg = (const float*)d_in[21], *xlb = (const float*)d_in[22];
    const float* elg = (const float*)d_in[23], *elb = (const float*)d_in[24];
    const float* d_w1 = (const float*)d_in[25], *d_b1 = (const float*)d_in[26];
    const float* d_w2 = (const float*)d_in[27], *d_b2 = (const float*)d_in[28];
    float* out = (float*)d_out;

    const int SM_NE  = (64 * 20 + 64 * 132 + 2 * 32 * HH) * 4;
    const int SM_EE  = (64 * 12 + 64 * 132 + 2 * 32 * HH) * 4;
    const int SM_LAY = (64 * 388 + 64 * 132 + 2 * 32 * HH) * 4 + 128 * 4;
    const int SM_DEC = (64 * 132 + 64 * 132 + 2 * 32 * HH + 256) * 4;
    cudaFuncSetAttribute(node_enc_kernel, cudaFuncAttributeMaxDynamicSharedMemorySize, SM_NE);
    cudaFuncSetAttribute(edge_enc_kernel, cudaFuncAttributeMaxDynamicSharedMemorySize, SM_EE);
    cudaFuncSetAttribute(layer_kernel,    cudaFuncAttributeMaxDynamicSharedMemorySize, SM_LAY);
    cudaFuncSetAttribute(decoder_kernel,  cudaFuncAttributeMaxDynamicSharedMemorySize, SM_DEC);

    detect_idx_kernel<<<1, 32>>>((const int*)eidx);
    convert_idx_kernel<<<(EE + 255) / 256, 256>>>(eidx);
    zero_hagg_kernel<<<(NN * HH / 4) / 256, 256>>>();

    node_enc_kernel<<<(NN + 63) / 64, 256, SM_NE>>>(x, nz, ne_w1, ne_b1, ne_w2, ne_b2);
    edge_enc_kernel<<<EE / 64, 256, SM_EE>>>(ea, ez, ee_w1, ee_b1, ee_w2, ee_b2);

    for (int l = 0; l < LL; l++) {
        layer_kernel<<<EE / 64, 256, SM_LAY>>>(ge_w1, ge_b1, ge_w2, ge_b2,
                                               gn_w1, gn_b1, gn_w2, gn_b2,
                                               elg + l * HH, elb + l * HH);
        node_ln_kernel<<<(NN + 63) / 64, 256>>>(xlg + l * HH, xlb + l * HH);
    }

    decoder_kernel<<<(NN + 63) / 64, 256, SM_DEC>>>(d_w1, d_b1, d_w2, d_b2, nz, out);
}